// round 2
// baseline (speedup 1.0000x reference)
#include <cuda_runtime.h>
#include <cuda_bf16.h>
#include <math.h>

// BidirectionalALiBi: out[h, i, j] = |j - i| * m
//   m = alpha[h] if (i==0 || j==0), gamma[h] if j>i, beta[h] if j<i.
// Piecewise-linear in j:
//   upper (j >= i):  v = fma(j,  g, -i*g)    (j==i gives 0)
//   lower (j <= i):  v = fma(j, -b,  i*b)    (j==i gives 0)
//   row i==0:        v = j * a
//   col j==0 (i>0):  v = i * a   (scalar fix-up on thread 0)
//
// One block per (h,i) row, 256 threads, 8 consecutive floats per thread
// (2x STG.128). Coefficients selected once per thread; only the single
// diagonal-straddling thread per row takes the per-element path.

__global__ void __launch_bounds__(256, 8)
alibi_kernel(const float* __restrict__ alpha,
             const float* __restrict__ beta,
             const float* __restrict__ gamma,
             float* __restrict__ out,
             int S, int log2S)
{
    const int row = blockIdx.x;            // row = h * S + i
    const int h = row >> log2S;
    const int i = row - (h << log2S);

    const float a = __ldg(&alpha[h]);
    const float b = __ldg(&beta[h]);
    const float g = __ldg(&gamma[h]);

    const int j0 = threadIdx.x << 3;       // 8 elements per thread
    const float fi = (float)i;

    float v[8];

    if (i == 0) {
        // whole row uses alpha; |j-0| = j
        float fj = (float)j0;
#pragma unroll
        for (int k = 0; k < 8; ++k) { v[k] = fj * a; fj += 1.0f; }
    } else if (j0 >= i) {
        // entirely upper (covers j==i -> 0)
        const float c0 = -fi * g;
        float fj = (float)j0;
#pragma unroll
        for (int k = 0; k < 8; ++k) { v[k] = fmaf(fj, g, c0); fj += 1.0f; }
    } else if (j0 + 7 <= i) {
        // entirely lower (covers j==i -> 0)
        const float c0 = fi * b;
        const float nb = -b;
        float fj = (float)j0;
#pragma unroll
        for (int k = 0; k < 8; ++k) { v[k] = fmaf(fj, nb, c0); fj += 1.0f; }
    } else {
        // straddles the diagonal: one thread per row
#pragma unroll
        for (int k = 0; k < 8; ++k) {
            const int j = j0 + k;
            const float fj = (float)j;
            const float m = (j > i) ? g : b;
            v[k] = fabsf(fj - fi) * m;
        }
    }

    // edge column j==0 (only matters when i != 0; i==0 case already 0)
    if (j0 == 0 && i != 0) v[0] = fi * a;

    float4* __restrict__ orow =
        reinterpret_cast<float4*>(out + (size_t)row * (size_t)S + j0);
    orow[0] = make_float4(v[0], v[1], v[2], v[3]);
    orow[1] = make_float4(v[4], v[5], v[6], v[7]);
}

extern "C" void kernel_launch(void* const* d_in, const int* in_sizes, int n_in,
                              void* d_out, int out_size)
{
    const float* alpha = (const float*)d_in[0];
    const float* beta  = (const float*)d_in[1];
    const float* gamma = (const float*)d_in[2];
    float* out = (float*)d_out;

    const int H = in_sizes[0];                 // 16
    long long ss = (long long)out_size / H;    // S*S
    int S = (int)(sqrt((double)ss) + 0.5);

    int log2S = 0;
    while ((1 << log2S) < S) ++log2S;          // S is a power of two (2048)

    const int threads = 256;                   // 8 floats per thread -> 2048 cols
    const int blocks = H * S;                  // one block per row

    alibi_kernel<<<blocks, threads>>>(alpha, beta, gamma, out, S, log2S);
}

// round 3
// speedup vs baseline: 1.4676x; 1.4676x over previous
#include <cuda_runtime.h>
#include <cuda_bf16.h>
#include <math.h>

// BidirectionalALiBi: out[h, i, j] = |j - i| * m
//   m = alpha[h] if (i==0 || j==0), gamma[h] if j>i, beta[h] if j<i.
//
// Linear-in-j form (i != 0):
//   upper (j >= i): v = fma(j,  g, -i*g)
//   lower (j <= i): v = fma(j, -b,  i*b)
//   row i==0:       v = j * a
//   col j==0, i>0:  v = i * a
//
// Layout lesson from R2: lane-contiguous float4 stores only. One block per
// row; 256 threads; thread t writes chunks at j = 4t and j = 4t + S/2.
// Both STG.128 are perfectly coalesced (warp covers 512B contiguous).

__device__ __forceinline__ float4
chunk_val(int i, float fi, int j0, float a, float b, float g)
{
    float4 r;
    const float fj = (float)j0;
    if (i == 0) {
        r.x = fj * a;
        r.y = (fj + 1.0f) * a;
        r.z = (fj + 2.0f) * a;
        r.w = (fj + 3.0f) * a;
        return r;
    }
    if (j0 >= i) {                       // entirely upper (diag -> 0)
        const float c0 = -fi * g;
        r.x = fmaf(fj,        g, c0);
        r.y = fmaf(fj + 1.0f, g, c0);
        r.z = fmaf(fj + 2.0f, g, c0);
        r.w = fmaf(fj + 3.0f, g, c0);
    } else if (j0 + 3 <= i) {            // entirely lower (diag -> 0)
        const float c0 = fi * b;
        const float nb = -b;
        r.x = fmaf(fj,        nb, c0);
        r.y = fmaf(fj + 1.0f, nb, c0);
        r.z = fmaf(fj + 2.0f, nb, c0);
        r.w = fmaf(fj + 3.0f, nb, c0);
    } else {                             // straddles diagonal (1 thread/row)
        float* rp = reinterpret_cast<float*>(&r);
#pragma unroll
        for (int k = 0; k < 4; ++k) {
            const int j = j0 + k;
            const float m = (j > i) ? g : b;
            rp[k] = fabsf((float)j - fi) * m;
        }
    }
    if (j0 == 0) r.x = fi * a;           // edge column j==0 (i != 0 here)
    return r;
}

__global__ void __launch_bounds__(256, 8)
alibi_kernel(const float* __restrict__ alpha,
             const float* __restrict__ beta,
             const float* __restrict__ gamma,
             float* __restrict__ out,
             int S, int log2S)
{
    const int row = blockIdx.x;            // row = h * S + i
    const int h = row >> log2S;
    const int i = row - (h << log2S);

    const float a = __ldg(&alpha[h]);
    const float b = __ldg(&beta[h]);
    const float g = __ldg(&gamma[h]);
    const float fi = (float)i;

    const int half = S >> 1;               // 1024
    const int jA = threadIdx.x << 2;       // chunk 0: [0, S/2)
    const int jB = jA + half;              // chunk 1: [S/2, S)

    const float4 vA = chunk_val(i, fi, jA, a, b, g);
    const float4 vB = chunk_val(i, fi, jB, a, b, g);

    float4* __restrict__ orow =
        reinterpret_cast<float4*>(out + (size_t)row * (size_t)S);
    orow[jA >> 2] = vA;
    orow[jB >> 2] = vB;
}

extern "C" void kernel_launch(void* const* d_in, const int* in_sizes, int n_in,
                              void* d_out, int out_size)
{
    const float* alpha = (const float*)d_in[0];
    const float* beta  = (const float*)d_in[1];
    const float* gamma = (const float*)d_in[2];
    float* out = (float*)d_out;

    const int H = in_sizes[0];                 // 16
    long long ss = (long long)out_size / H;    // S*S
    int S = (int)(sqrt((double)ss) + 0.5);

    int log2S = 0;
    while ((1 << log2S) < S) ++log2S;          // S is a power of two (2048)

    const int threads = 256;
    const int blocks = H * S;                  // one block per row

    alibi_kernel<<<blocks, threads>>>(alpha, beta, gamma, out, S, log2S);
}